// round 9
// baseline (speedup 1.0000x reference)
#include <cuda_runtime.h>
#include <cuda_bf16.h>
#include <cub/cub.cuh>
#include <cstdint>

#define ALPHA_F 10.0f
#define DELTA_F 0.0005f
#define NB      4194304          // 2^22 value-based buckets
#define NBF     4194304.0f

// ---- scratch (device globals: allocation-free rule) ----
__device__ unsigned long long g_pairs[16777216];   // 134 MB dense (keybits<<32 | idx)
__device__ int                g_bkt[NB];           // 16 MB: counts -> starts -> ends
__device__ unsigned char      g_temp[8u * 1024u * 1024u]; // CUB DeviceScan temp
__device__ double             g_accum;

__device__ __forceinline__ float clampf01(float x) {
    return fminf(fmaxf(x, 0.0f), 1.0f);
}
__device__ __forceinline__ int bucket_of(float x) {   // monotone non-decreasing in x
    int b = (int)(x * NBF);
    return min(max(b, 0), NB - 1);
}

__global__ void k_zero_acc() { g_accum = 0.0; }

__global__ __launch_bounds__(256) void k_hist(const float4* __restrict__ in4, int n4) {
    int t = blockIdx.x * blockDim.x + threadIdx.x;
    if (t >= n4) return;
    float4 v = __ldg(&in4[t]);
    atomicAdd(&g_bkt[bucket_of(clampf01(v.x))], 1);
    atomicAdd(&g_bkt[bucket_of(clampf01(v.y))], 1);
    atomicAdd(&g_bkt[bucket_of(clampf01(v.z))], 1);
    atomicAdd(&g_bkt[bucket_of(clampf01(v.w))], 1);
}

__global__ __launch_bounds__(256) void k_scatter(const float4* __restrict__ in4, int n4) {
    int t = blockIdx.x * blockDim.x + threadIdx.x;
    if (t >= n4) return;
    float4 v = __ldg(&in4[t]);
    unsigned int i0 = (unsigned int)t * 4u;
    float c[4] = {clampf01(v.x), clampf01(v.y), clampf01(v.z), clampf01(v.w)};
    #pragma unroll
    for (int u = 0; u < 4; u++) {
        int b = bucket_of(c[u]);
        int pos = atomicAdd(&g_bkt[b], 1);           // g_bkt holds starts -> becomes ends
        unsigned int kb = __float_as_uint(c[u]);     // c >= 0 -> bits monotone in value
        g_pairs[pos] = ((unsigned long long)kb << 32) | (unsigned long long)(i0 + u);
    }
}

// Exact np.interp: pred = max (key,idx) with key <= q; succ = min (key,idx) with key > q.
// Packed-u64 max/min gives exactly the stable-sort tie order. Bucket order = key order,
// so pred lives in the highest bucket <= b containing a key <= q; succ symmetric.
// Missing pred -> left fill = y(succ); missing succ -> right fill = y(pred).
__device__ __forceinline__ float eval_f(float q, const float* __restrict__ arr) {
    int b = bucket_of(q);
    int s = (b == 0) ? 0 : __ldg(&g_bkt[b - 1]);
    int e = __ldg(&g_bkt[b]);

    unsigned long long pred = 0, succ = 0;
    bool hasP = false, hasS = false;
    for (int p = s; p < e; p++) {
        unsigned long long pr = __ldg(&g_pairs[p]);
        float k = __uint_as_float((unsigned int)(pr >> 32));
        if (k <= q) { if (!hasP || pr > pred) { pred = pr; hasP = true; } }
        else        { if (!hasS || pr < succ) { succ = pr; hasS = true; } }
    }
    if (!hasP) {                 // walk down: max of first non-empty lower bucket
        int bb = b - 1;
        while (bb >= 0) {
            int ss = (bb == 0) ? 0 : __ldg(&g_bkt[bb - 1]);
            int ee = __ldg(&g_bkt[bb]);
            if (ee > ss) {
                for (int p = ss; p < ee; p++) {
                    unsigned long long pr = __ldg(&g_pairs[p]);
                    if (!hasP || pr > pred) { pred = pr; hasP = true; }
                }
                break;
            }
            bb--;
        }
    }
    if (!hasS) {                 // walk up: min of first non-empty higher bucket
        int bb = b + 1;
        while (bb < NB) {
            int ss = __ldg(&g_bkt[bb - 1]);
            int ee = __ldg(&g_bkt[bb]);
            if (ee > ss) {
                for (int p = ss; p < ee; p++) {
                    unsigned long long pr = __ldg(&g_pairs[p]);
                    if (!hasS || pr < succ) { succ = pr; hasS = true; }
                }
                break;
            }
            bb++;
        }
    }
    if (!hasP) return __ldg(&arr[(unsigned int)(succ & 0xFFFFFFFFu)]);   // q below all knots
    if (!hasS) return __ldg(&arr[(unsigned int)(pred & 0xFFFFFFFFu)]);   // q above all knots
    float x0 = __uint_as_float((unsigned int)(pred >> 32));
    float x1 = __uint_as_float((unsigned int)(succ >> 32));
    float y0 = __ldg(&arr[(unsigned int)(pred & 0xFFFFFFFFu)]);
    float y1 = __ldg(&arr[(unsigned int)(succ & 0xFFFFFFFFu)]);
    return y0 + (q - x0) * (y1 - y0) / (x1 - x0);    // x1 > q >= x0 -> no div0
}

// gap_i = relu(f(c_i + d) - f(c_{i+1} - d)); direct, original order, no scatter
__global__ __launch_bounds__(256) void k_eval(const float* __restrict__ ind,
                                              const float* __restrict__ arr, int n) {
    int i = blockIdx.x * blockDim.x + threadIdx.x;
    float gap = 0.0f;
    if (i < n - 1) {
        float ci = clampf01(__ldg(&ind[i]));
        float cn = clampf01(__ldg(&ind[i + 1]));
        float A = eval_f(ci + DELTA_F, arr);
        float B = eval_f(cn - DELTA_F, arr);
        gap = fmaxf(A - B, 0.0f);
    }
    typedef cub::BlockReduce<float, 256> BR;
    __shared__ typename BR::TempStorage ts;
    float s = BR(ts).Sum(gap);
    if (threadIdx.x == 0) atomicAdd(&g_accum, (double)s);
}

__global__ void k_final(float* __restrict__ out) {
    out[0] = (float)((double)ALPHA_F * g_accum);
}

extern "C" void kernel_launch(void* const* d_in, const int* in_sizes, int n_in,
                              void* d_out, int out_size) {
    const float* indices = (const float*)d_in[0];
    const float* array   = (const float*)d_in[1];
    int n = in_sizes[0];

    int* p_bkt = nullptr;
    void* p_temp = nullptr;
    cudaGetSymbolAddress((void**)&p_bkt, g_bkt);
    cudaGetSymbolAddress(&p_temp, g_temp);

    const int threads = 256;
    int n4 = n / 4;
    int b4 = (n4 + threads - 1) / threads;

    // 0) zero accumulator + counts
    k_zero_acc<<<1, 1>>>();
    cudaMemsetAsync(p_bkt, 0, (size_t)NB * sizeof(int));

    // 1) histogram over value-based buckets
    k_hist<<<b4, threads>>>((const float4*)indices, n4);

    // 2) exclusive scan (in-place): counts -> starts
    size_t temp_bytes = sizeof(g_temp);
    cub::DeviceScan::ExclusiveSum(p_temp, temp_bytes, p_bkt, p_bkt, NB);

    // 3) scatter packed (keybits, idx) into dense buckets; starts -> ends
    k_scatter<<<b4, threads>>>((const float4*)indices, n4);

    // 4) eval both shifted queries per gap + reduce (exact pred/succ from buckets)
    k_eval<<<(n - 1 + threads - 1) / threads, threads>>>(indices, array, n);

    // 5) scale + write scalar output
    k_final<<<1, 1>>>((float*)d_out);
}

// round 10
// speedup vs baseline: 1.8669x; 1.8669x over previous
#include <cuda_runtime.h>
#include <cuda_bf16.h>
#include <cub/cub.cuh>
#include <cstdint>

#define ALPHA_F 10.0f
#define DELTA_F 0.0005f
#define ITEMS 8
#define SEED_OFF 8389          // delta * N for N=2^24; verified at runtime, fallback-safe
#define SEED_HALF 1024

// ---- scratch (device globals: allocation-free rule) ----
__device__ float        g_clamped[16777216];
__device__ float        g_xs[16777216];
__device__ unsigned int g_idx_in[16777216];
__device__ unsigned int g_idx[16777216];
__device__ float        g_ys[16777216];
__device__ float2       g_AB[16777216];
__device__ unsigned char g_temp[200u * 1024u * 1024u];
__device__ double       g_accum;

__global__ __launch_bounds__(256) void k_init(const float4* __restrict__ in4, int n4) {
    int t = blockIdx.x * blockDim.x + threadIdx.x;
    if (t == 0) g_accum = 0.0;
    if (t >= n4) return;
    float4 v = __ldg(&in4[t]);
    float4 c;
    c.x = fminf(fmaxf(v.x, 0.0f), 1.0f);
    c.y = fminf(fmaxf(v.y, 0.0f), 1.0f);
    c.z = fminf(fmaxf(v.z, 0.0f), 1.0f);
    c.w = fminf(fmaxf(v.w, 0.0f), 1.0f);
    ((float4*)g_clamped)[t] = c;
    unsigned int i0 = (unsigned int)t * 4u;
    ((uint4*)g_idx_in)[t] = make_uint4(i0, i0 + 1, i0 + 2, i0 + 3);
}

__global__ __launch_bounds__(256) void k_gather(const float* __restrict__ array, int n4) {
    int t = blockIdx.x * blockDim.x + threadIdx.x;
    if (t >= n4) return;
    uint4 id = __ldg(&((const uint4*)g_idx)[t]);
    float4 y;
    y.x = __ldg(&array[id.x]);
    y.y = __ldg(&array[id.y]);
    y.z = __ldg(&array[id.z]);
    y.w = __ldg(&array[id.w]);
    ((float4*)g_ys)[t] = y;
}

// first index in [lo,hi) with xs > q  (caller guarantees invariants on lo/hi)
__device__ __forceinline__ int bsearch_gt(float q, int lo, int hi) {
    while (lo < hi) {
        int mid = (lo + hi) >> 1;
        if (__ldg(&g_xs[mid]) <= q) lo = mid + 1; else hi = mid;
    }
    return lo;
}

// Each thread owns ITEMS consecutive sorted positions; bracket indices are
// monotone in k. One seeded/galloped search per side per thread, then linear
// advance. np.interp semantics: j = last index with xs[j] <= q.
__global__ __launch_bounds__(256) void k_interp(int n) {
    const int base = (blockIdx.x * 256 + threadIdx.x) * ITEMS;
    if (base >= n) return;
    const int m = (n - base < ITEMS) ? (n - base) : ITEMS;

    float xk[ITEMS];
    #pragma unroll
    for (int t = 0; t < ITEMS; t++)
        xk[t] = (t < m) ? __ldg(&g_xs[base + t]) : 0.0f;

    float A[ITEMS], B[ITEMS];

    // ---------- side A: q = xk + delta, bracket >= base ----------
    {
        float q0 = xk[0] + DELTA_F;
        int w_lo = base + SEED_OFF - SEED_HALF; if (w_lo < base) w_lo = base;
        int w_hi = base + SEED_OFF + SEED_HALF; if (w_hi > n) w_hi = n;
        int lo;
        bool ok_lo = (w_lo == base) || (w_lo < n && __ldg(&g_xs[w_lo]) <= q0);
        bool ok_hi = (w_hi == n)   || (__ldg(&g_xs[w_hi]) > q0);
        if (ok_lo && ok_hi && w_lo <= w_hi) {
            lo = bsearch_gt(q0, w_lo, w_hi);
        } else {                                   // general-input fallback
            int off = 8192;
            while (base + off < n && __ldg(&g_xs[base + off]) <= q0) off <<= 1;
            int hi = (base + off < n) ? (base + off) : n;
            lo = bsearch_gt(q0, base, hi);
        }
        int jA = lo - 1;
        #pragma unroll
        for (int t = 0; t < ITEMS; t++) {
            if (t >= m) break;
            float q = xk[t] + DELTA_F;
            while (jA + 1 < n && __ldg(&g_xs[jA + 1]) <= q) jA++;
            if (jA >= n - 1) {
                A[t] = __ldg(&g_ys[n - 1]);
            } else {
                float x0 = __ldg(&g_xs[jA]), x1 = __ldg(&g_xs[jA + 1]);
                float y0 = __ldg(&g_ys[jA]), y1 = __ldg(&g_ys[jA + 1]);
                A[t] = y0 + (q - x0) * (y1 - y0) / (x1 - x0);
            }
        }
    }

    // ---------- side B: q = xk - delta, bracket <= base-1 ----------
    {
        float q0 = xk[0] - DELTA_F;
        int w_lo = base - SEED_OFF - SEED_HALF; if (w_lo < 0) w_lo = 0;
        int w_hi = base - SEED_OFF + SEED_HALF; if (w_hi > base) w_hi = base; if (w_hi < 0) w_hi = 0;
        int lo;
        bool ok_lo = (w_lo == 0)    || (__ldg(&g_xs[w_lo]) <= q0);
        bool ok_hi = (w_hi == base) || (__ldg(&g_xs[w_hi]) > q0);
        if (ok_lo && ok_hi && w_lo <= w_hi) {
            lo = bsearch_gt(q0, w_lo, w_hi);
        } else {                                   // general-input fallback
            int off = 8192;
            while (base - off >= 0 && __ldg(&g_xs[base - off]) > q0) off <<= 1;
            int l2 = (base - off > 0) ? (base - off) : 0;
            lo = bsearch_gt(q0, l2, base);
        }
        int jB = lo - 1;
        #pragma unroll
        for (int t = 0; t < ITEMS; t++) {
            if (t >= m) break;
            float q = xk[t] - DELTA_F;
            while (jB + 1 < n && __ldg(&g_xs[jB + 1]) <= q) jB++;
            if (jB < 0) {
                B[t] = __ldg(&g_ys[0]);
            } else if (jB >= n - 1) {
                B[t] = __ldg(&g_ys[n - 1]);
            } else {
                float x0 = __ldg(&g_xs[jB]), x1 = __ldg(&g_xs[jB + 1]);
                float y0 = __ldg(&g_ys[jB]), y1 = __ldg(&g_ys[jB + 1]);
                B[t] = y0 + (q - x0) * (y1 - y0) / (x1 - x0);
            }
        }
    }

    // streaming scatter to original positions (bypass L2 persistence)
    #pragma unroll
    for (int t = 0; t < ITEMS; t++) {
        if (t >= m) break;
        unsigned int o = __ldg(&g_idx[base + t]);
        __stcs(&g_AB[o], make_float2(A[t], B[t]));
    }
}

// gap_i = relu(AB[i].x - AB[i+1].y); grid-stride, 2 gaps per float4
__global__ __launch_bounds__(256) void k_gap(int n) {
    float acc = 0.0f;
    int stride = gridDim.x * blockDim.x;
    for (int t = blockIdx.x * blockDim.x + threadIdx.x; 2 * t < n - 1; t += stride) {
        int i = 2 * t;
        float4 ab = __ldcs((const float4*)&g_AB[i]);   // A_i,B_i,A_{i+1},B_{i+1}
        acc += fmaxf(ab.x - ab.w, 0.0f);
        if (i + 2 < n) {
            float2 nx = __ldcs(&g_AB[i + 2]);
            acc += fmaxf(ab.z - nx.y, 0.0f);
        }
    }
    typedef cub::BlockReduce<float, 256> BR;
    __shared__ typename BR::TempStorage ts;
    float s = BR(ts).Sum(acc);
    if (threadIdx.x == 0) atomicAdd(&g_accum, (double)s);
}

__global__ void k_final(float* __restrict__ out) {
    out[0] = (float)((double)ALPHA_F * g_accum);
}

extern "C" void kernel_launch(void* const* d_in, const int* in_sizes, int n_in,
                              void* d_out, int out_size) {
    const float* indices = (const float*)d_in[0];
    const float* array   = (const float*)d_in[1];
    int n = in_sizes[0];

    float* p_clamped = nullptr;
    float* p_xs = nullptr;
    unsigned int* p_idx_in = nullptr;
    unsigned int* p_idx = nullptr;
    void*  p_temp = nullptr;
    cudaGetSymbolAddress((void**)&p_clamped, g_clamped);
    cudaGetSymbolAddress((void**)&p_xs, g_xs);
    cudaGetSymbolAddress((void**)&p_idx_in, g_idx_in);
    cudaGetSymbolAddress((void**)&p_idx, g_idx);
    cudaGetSymbolAddress(&p_temp, g_temp);

    const int threads = 256;
    int n4 = n / 4;
    int b4 = (n4 + threads - 1) / threads;

    // 1) clamp + iota (vectorized) + zero accumulator
    k_init<<<b4, threads>>>((const float4*)indices, n4);

    // 2) full 32-bit stable sort (exact order is load-bearing; R8 proved it)
    size_t temp_bytes = sizeof(g_temp);
    cub::DeviceRadixSort::SortPairs(p_temp, temp_bytes,
                                    p_clamped, p_xs,
                                    p_idx_in, p_idx,
                                    n, 0, 32);

    // 3) gather y-values into sorted order (vectorized idx read)
    k_gather<<<b4, threads>>>(array, n4);

    // 4) sorted-domain merge-interpolation (seeded search), streaming AB scatter
    int chunk_blocks = (n + threads * ITEMS - 1) / (threads * ITEMS);
    k_interp<<<chunk_blocks, threads>>>(n);

    // 5) gap + reduction
    k_gap<<<592, threads>>>(n);

    // 6) scale + write scalar output
    k_final<<<1, 1>>>((float*)d_out);
}